// round 16
// baseline (speedup 1.0000x reference)
#include <cuda_runtime.h>
#include <math_constants.h>
#include <cstdint>

#define BB 32
#define SS 480
#define DD 512
#define HH 8
#define DK 64
#define ML 500
#define QT 32
#define JT 128
#define QB 64       // scores row band
#define QBP 68      // qsT row stride
#define JTP 132
#define PVQ 128
#define PVP 132

__device__ float g_q[BB*HH*SS*DK];
__device__ float g_k[BB*HH*SS*DK];
__device__ float g_v[BB*HH*SS*DK];
__device__ float g_ctx[(size_t)BB*SS*DD];
__device__ float g_p[(size_t)BB*HH*SS*SS];   // probs (normalized in-kernel)

// ---------------------------------------------------------------------------
// Kernel 1: fused QKV projection (R10/R14 version — known good).
// ---------------------------------------------------------------------------
__global__ __launch_bounds__(128) void proj_qkv(
    const float* __restrict__ x,
    const float* __restrict__ wq, const float* __restrict__ bq,
    const float* __restrict__ wk, const float* __restrict__ bk,
    const float* __restrict__ wv, const float* __restrict__ bv)
{
    const int z = blockIdx.z;
    const float* W    = (z == 0) ? wq : (z == 1) ? wk : wv;
    const float* bias = (z == 0) ? bq : (z == 1) ? bk : bv;
    float* Out        = (z == 0) ? g_q : (z == 1) ? g_k : g_v;

    __shared__ float Xs[32][132];
    __shared__ float Ws[32][68];

    const int m0 = blockIdx.x * 64;
    const int n0 = blockIdx.y * 128;
    const int tid = threadIdx.x;

    const int c8 = tid & 7,  xrow = tid >> 3;
    const int wc4 = tid & 15, wk_ = tid >> 4;
    const int ri = tid >> 3, ci = tid & 7;

    float acc[8][8] = {};
    float4 xr[8], wr[4];

#pragma unroll
    for (int rr = 0; rr < 8; rr++)
        xr[rr] = *(const float4*)&x[(size_t)(n0 + xrow + rr*16)*DD + c8*4];
#pragma unroll
    for (int tt = 0; tt < 4; tt++)
        wr[tt] = *(const float4*)&W[(size_t)(wk_ + tt*8)*DD + m0 + wc4*4];

    for (int k0 = 0; k0 < DD; k0 += 32) {
#pragma unroll
        for (int rr = 0; rr < 8; rr++) {
            int r = xrow + rr*16;
            Xs[c8*4+0][r] = xr[rr].x; Xs[c8*4+1][r] = xr[rr].y;
            Xs[c8*4+2][r] = xr[rr].z; Xs[c8*4+3][r] = xr[rr].w;
        }
#pragma unroll
        for (int tt = 0; tt < 4; tt++)
            *(float4*)&Ws[wk_ + tt*8][wc4*4] = wr[tt];
        __syncthreads();

        if (k0 + 32 < DD) {
#pragma unroll
            for (int rr = 0; rr < 8; rr++)
                xr[rr] = *(const float4*)&x[(size_t)(n0 + xrow + rr*16)*DD + k0 + 32 + c8*4];
#pragma unroll
            for (int tt = 0; tt < 4; tt++)
                wr[tt] = *(const float4*)&W[(size_t)(k0 + 32 + wk_ + tt*8)*DD + m0 + wc4*4];
        }

#pragma unroll
        for (int t = 0; t < 32; t++) {
            float4 a0 = *(const float4*)&Xs[t][ri*8];
            float4 a1 = *(const float4*)&Xs[t][ri*8+4];
            float4 b0 = *(const float4*)&Ws[t][ci*8];
            float4 b1 = *(const float4*)&Ws[t][ci*8+4];
            float av[8] = {a0.x,a0.y,a0.z,a0.w,a1.x,a1.y,a1.z,a1.w};
            float bw[8] = {b0.x,b0.y,b0.z,b0.w,b1.x,b1.y,b1.z,b1.w};
#pragma unroll
            for (int i = 0; i < 8; i++)
#pragma unroll
                for (int j = 0; j < 8; j++)
                    acc[i][j] += av[i] * bw[j];
        }
        __syncthreads();
    }

    const int h = m0 >> 6;
    const int d = ci*8;
    float4 bb0 = *(const float4*)&bias[m0 + d];
    float4 bb1 = *(const float4*)&bias[m0 + d + 4];
#pragma unroll
    for (int u = 0; u < 8; u++) {
        int n = n0 + ri*8 + u;
        int b = n / SS, s = n % SS;
        float* dst = &Out[(((size_t)b*HH + h)*SS + s)*DK + d];
        *(float4*)&dst[0] = make_float4(acc[u][0]+bb0.x, acc[u][1]+bb0.y,
                                        acc[u][2]+bb0.z, acc[u][3]+bb0.w);
        *(float4*)&dst[4] = make_float4(acc[u][4]+bb1.x, acc[u][5]+bb1.y,
                                        acc[u][6]+bb1.z, acc[u][7]+bb1.w);
    }
}

// ---------------------------------------------------------------------------
// Kernel 2: scores GEMM + fused softmax.  64-row bands (R14 GEMM phase),
// then phase-2 in-CTA row softmax over the freshly written (L2-hot) band.
// ---------------------------------------------------------------------------
__global__ __launch_bounds__(256) void scores_gemm(
    const float* __restrict__ rel_bias)
{
    __shared__ float qsT[64*QBP];    // [t][i], i < 64
    __shared__ float kvb[64*JTP];    // [t][j]

    const int i0 = blockIdx.x * QB;
    const int h  = blockIdx.y;
    const int b  = blockIdx.z;
    const int tid = threadIdx.x;
    const int lane = tid & 31, warp = tid >> 5;

    const int rows   = min(QB, SS - i0);
    const int jcount = min(i0 + QB, SS);
    const int ntile  = (jcount + JT - 1) / JT;

    const float* qg = g_q + (((size_t)b*HH + h)*SS + i0)*DK;
    const float* kg = g_k + (((size_t)b*HH + h)*SS)*DK;
    float* sg = g_p + (((size_t)b*HH + h)*SS + i0)*SS;

    // q band transposed
#pragma unroll
    for (int it = 0; it < 16; it++) {
        int idx = tid + it*256;
        int i = idx >> 6, t = idx & 63;
        qsT[t*QBP + i] = (i < rows) ? qg[(size_t)i*DK + t] : 0.f;
    }

    const int ig = tid >> 4;      // 16 groups of 4 rows
    const int jg = tid & 15;      // j cols jg*4 and 64+jg*4

    for (int jt = 0; jt < ntile; jt++) {
        const int j0 = jt * JT;
        __syncthreads();
#pragma unroll
        for (int it = 0; it < 32; it++) {
            int idx = tid + it*256;
            int jl = idx >> 6, t = idx & 63;
            int j = j0 + jl;
            kvb[t*JTP + jl] = (j < SS) ? kg[(size_t)j*DK + t] : 0.f;
        }
        __syncthreads();

        float acc[4][8] = {};
#pragma unroll
        for (int t = 0; t < 64; t++) {
            float4 a4 = *(const float4*)&qsT[t*QBP + ig*4];
            float4 b0 = *(const float4*)&kvb[t*JTP + jg*4];
            float4 b1 = *(const float4*)&kvb[t*JTP + 64 + jg*4];
            float av[4] = {a4.x, a4.y, a4.z, a4.w};
            float bw[8] = {b0.x,b0.y,b0.z,b0.w,b1.x,b1.y,b1.z,b1.w};
#pragma unroll
            for (int i = 0; i < 4; i++)
#pragma unroll
                for (int c = 0; c < 8; c++)
                    acc[i][c] += av[i] * bw[c];
        }

#pragma unroll
        for (int ii = 0; ii < 4; ii++) {
            const int il = ig*4 + ii;
            if (il >= rows) break;
            const int i = i0 + il;
            const float* brow = rel_bias + ((size_t)h*ML + i)*ML;
            float* srow = sg + (size_t)il*SS;
#pragma unroll
            for (int half = 0; half < 2; half++) {
                const int jb = j0 + half*64 + jg*4;
                float vals[4];
#pragma unroll
                for (int jj = 0; jj < 4; jj++) {
                    int j = jb + jj;
                    vals[jj] = (j <= i && j < SS) ? acc[ii][half*4+jj]*0.125f + brow[j]
                                                  : -CUDART_INF_F;
                }
                if (jb + 3 < SS)
                    *(float4*)&srow[jb] = make_float4(vals[0], vals[1], vals[2], vals[3]);
                else {
#pragma unroll
                    for (int jj = 0; jj < 4; jj++)
                        if (jb + jj < SS) srow[jb + jj] = vals[jj];
                }
            }
        }
    }

    // ----- phase 2: fused row softmax over this band (L2-hot re-read) -----
    __syncthreads();
    for (int r = warp; r < rows; r += 8) {
        const int i = i0 + r;
        const int n = i + 1;                    // valid cols
        float* row = sg + (size_t)r*SS;

        float v[15];
        float m = -CUDART_INF_F;
#pragma unroll
        for (int k = 0; k < 15; k++) {
            int j = lane + k*32;
            v[k] = (j < n) ? row[j] : -CUDART_INF_F;
            m = fmaxf(m, v[k]);
        }
#pragma unroll
        for (int o = 16; o; o >>= 1) m = fmaxf(m, __shfl_xor_sync(0xffffffffu, m, o));

        float s = 0.f;
#pragma unroll
        for (int k = 0; k < 15; k++) {
            int j = lane + k*32;
            v[k] = (j < n) ? __expf(v[k] - m) : 0.f;
            s += v[k];
        }
#pragma unroll
        for (int o = 16; o; o >>= 1) s += __shfl_xor_sync(0xffffffffu, s, o);
        float inv = 1.f / s;

#pragma unroll
        for (int k = 0; k < 15; k++) {
            int j = lane + k*32;
            if (j < SS) row[j] = v[k] * inv;    // zeros above diagonal
        }
    }
}

// ---------------------------------------------------------------------------
// Kernel 3: attn mean over heads (unchanged — 75% DRAM).
// ---------------------------------------------------------------------------
__global__ __launch_bounds__(256) void mean_kernel(float* __restrict__ out_attn)
{
    const int gid = blockIdx.x * 256 + threadIdx.x;
    const int j4  = gid % (SS/4);
    int rest = gid / (SS/4);
    const int i = rest % SS;
    const int b = rest / SS;

    const int i0 = (i >> 5) << 5;
    const int jcap = min(SS, (((i0 + QT) + JT - 1) / JT) * JT);

    float4 s = make_float4(0.f, 0.f, 0.f, 0.f);
    if (j4*4 < jcap) {
        const float* base = g_p + (((size_t)b*HH)*SS + i)*SS + j4*4;
#pragma unroll
        for (int h = 0; h < HH; h++) {
            float4 v = *(const float4*)(base + (size_t)h*SS*SS);
            s.x += v.x; s.y += v.y; s.z += v.z; s.w += v.w;
        }
        s.x *= 0.125f; s.y *= 0.125f; s.z *= 0.125f; s.w *= 0.125f;
    }
    *(float4*)&out_attn[((size_t)b*SS + i)*SS + j4*4] = s;
}

// ---------------------------------------------------------------------------
// Kernel 4: ctx = P @ V.  (R12/R14 version — best measured)
// ---------------------------------------------------------------------------
__global__ __launch_bounds__(256, 2) void pv_kernel()
{
    extern __shared__ float pvsm[];
    float* psT = pvsm;
    float* vs  = psT + JT*PVP;

    const int i0 = blockIdx.x * PVQ;
    const int h  = blockIdx.y;
    const int b  = blockIdx.z;
    const int tid = threadIdx.x;

    const int jcount = min(i0 + PVQ, SS);
    const int ntile  = (jcount + JT - 1) / JT;

    const float* vg = g_v + (((size_t)b*HH + h)*SS)*DK;
    const float* pg = g_p + (((size_t)b*HH + h)*SS + i0)*SS;

    const int rg = tid >> 4;
    const int cg = tid & 15;

    float acc[8][4] = {};

    for (int jt = 0; jt < ntile; jt++) {
        const int j0 = jt * JT;
        __syncthreads();
#pragma unroll
        for (int it = 0; it < 8; it++) {
            int idx = tid + it*256;
            int j = idx >> 4, d4 = idx & 15;
            float4 v = (j0 + j < SS)
                ? *(const float4*)&vg[(size_t)(j0 + j)*DK + d4*4]
                : make_float4(0.f,0.f,0.f,0.f);
            *(float4*)&vs[j*64 + d4*4] = v;
        }
#pragma unroll
        for (int it = 0; it < 64; it++) {
            int idx = tid + it*256;
            int r = idx >> 7, j = idx & 127;
            float p = (i0 + r < SS && j0 + j < SS) ? pg[(size_t)r*SS + j0 + j] : 0.f;
            psT[j*PVP + r] = p;
        }
        __syncthreads();

#pragma unroll 4
        for (int j = 0; j < JT; j++) {
            float4 a0 = *(const float4*)&psT[j*PVP + rg*8];
            float4 a1 = *(const float4*)&psT[j*PVP + rg*8 + 4];
            float4 b4 = *(const float4*)&vs[j*64 + cg*4];
            float av[8] = {a0.x,a0.y,a0.z,a0.w,a1.x,a1.y,a1.z,a1.w};
            float bw[4] = {b4.x,b4.y,b4.z,b4.w};
#pragma unroll
            for (int i = 0; i < 8; i++)
#pragma unroll
                for (int c = 0; c < 4; c++)
                    acc[i][c] += av[i] * bw[c];
        }
    }

#pragma unroll
    for (int i = 0; i < 8; i++) {
        int row = i0 + rg*8 + i;
        if (row < SS) {
            float* dst = g_ctx + ((size_t)b*SS + row)*DD + h*DK + cg*4;
            *(float4*)dst = make_float4(acc[i][0], acc[i][1], acc[i][2], acc[i][3]);
        }
    }
}

// ---------------------------------------------------------------------------
// Kernel 5: output projection (R10/R14 version).
// ---------------------------------------------------------------------------
__global__ __launch_bounds__(128) void out_proj(
    const float* __restrict__ wo, const float* __restrict__ bo,
    float* __restrict__ out)
{
    __shared__ float Xs[32][132];
    __shared__ float Ws[32][68];

    const int m0 = blockIdx.x * 64;
    const int n0 = blockIdx.y * 128;
    const int tid = threadIdx.x;

    const int c8 = tid & 7,  xrow = tid >> 3;
    const int wc4 = tid & 15, wk_ = tid >> 4;
    const int ri = tid >> 3, ci = tid & 7;

    float acc[8][8] = {};
    float4 xr[8], wr[4];

#pragma unroll
    for (int rr = 0; rr < 8; rr++)
        xr[rr] = *(const float4*)&g_ctx[(size_t)(n0 + xrow + rr*16)*DD + c8*4];
#pragma unroll
    for (int tt = 0; tt < 4; tt++)
        wr[tt] = *(const float4*)&wo[(size_t)(wk_ + tt*8)*DD + m0 + wc4*4];

    for (int k0 = 0; k0 < DD; k0 += 32) {
#pragma unroll
        for (int rr = 0; rr < 8; rr++) {
            int r = xrow + rr*16;
            Xs[c8*4+0][r] = xr[rr].x; Xs[c8*4+1][r] = xr[rr].y;
            Xs[c8*4+2][r] = xr[rr].z; Xs[c8*4+3][r] = xr[rr].w;
        }
#pragma unroll
        for (int tt = 0; tt < 4; tt++)
            *(float4*)&Ws[wk_ + tt*8][wc4*4] = wr[tt];
        __syncthreads();

        if (k0 + 32 < DD) {
#pragma unroll
            for (int rr = 0; rr < 8; rr++)
                xr[rr] = *(const float4*)&g_ctx[(size_t)(n0 + xrow + rr*16)*DD + k0 + 32 + c8*4];
#pragma unroll
            for (int tt = 0; tt < 4; tt++)
                wr[tt] = *(const float4*)&wo[(size_t)(k0 + 32 + wk_ + tt*8)*DD + m0 + wc4*4];
        }

#pragma unroll
        for (int t = 0; t < 32; t++) {
            float4 a0 = *(const float4*)&Xs[t][ri*8];
            float4 a1 = *(const float4*)&Xs[t][ri*8+4];
            float4 b0 = *(const float4*)&Ws[t][ci*8];
            float4 b1 = *(const float4*)&Ws[t][ci*8+4];
            float av[8] = {a0.x,a0.y,a0.z,a0.w,a1.x,a1.y,a1.z,a1.w};
            float bw[8] = {b0.x,b0.y,b0.z,b0.w,b1.x,b1.y,b1.z,b1.w};
#pragma unroll
            for (int i = 0; i < 8; i++)
#pragma unroll
                for (int j = 0; j < 8; j++)
                    acc[i][j] += av[i] * bw[j];
        }
        __syncthreads();
    }

    const int d = ci*8;
    float4 bb0 = *(const float4*)&bo[m0 + d];
    float4 bb1 = *(const float4*)&bo[m0 + d + 4];
#pragma unroll
    for (int u = 0; u < 8; u++) {
        int n = n0 + ri*8 + u;
        float* dst = &out[(size_t)n*DD + m0 + d];
        *(float4*)&dst[0] = make_float4(acc[u][0]+bb0.x, acc[u][1]+bb0.y,
                                        acc[u][2]+bb0.z, acc[u][3]+bb0.w);
        *(float4*)&dst[4] = make_float4(acc[u][4]+bb1.x, acc[u][5]+bb1.y,
                                        acc[u][6]+bb1.z, acc[u][7]+bb1.w);
    }
}

// ---------------------------------------------------------------------------

static const int PV_SMEM = (JT*PVP + JT*64) * (int)sizeof(float);   // 100352

extern "C" void kernel_launch(void* const* d_in, const int* in_sizes, int n_in,
                              void* d_out, int out_size) {
    const float* x  = (const float*)d_in[0];
    const float* wq = (const float*)d_in[1];
    const float* bq = (const float*)d_in[2];
    const float* wk = (const float*)d_in[3];
    const float* bk = (const float*)d_in[4];
    const float* wv = (const float*)d_in[5];
    const float* bv = (const float*)d_in[6];
    const float* wo = (const float*)d_in[7];
    const float* bo = (const float*)d_in[8];
    const float* rb = (const float*)d_in[9];

    float* out      = (float*)d_out;
    float* out_attn = out + (size_t)BB*SS*DD;

    cudaFuncSetAttribute(pv_kernel, cudaFuncAttributeMaxDynamicSharedMemorySize, PV_SMEM);

    proj_qkv<<<dim3(DD/64, (BB*SS)/128, 3), 128>>>(x, wq, bq, wk, bk, wv, bv);

    scores_gemm<<<dim3((SS + QB - 1)/QB, HH, BB), 256>>>(rb);

    mean_kernel<<<(BB*SS*(SS/4))/256, 256>>>(out_attn);

    pv_kernel<<<dim3((SS + PVQ - 1)/PVQ, HH, BB), 256, PV_SMEM>>>();

    out_proj<<<dim3(DD/64, (BB*SS)/128), 128>>>(wo, bo, out);
}

// round 17
// speedup vs baseline: 1.0707x; 1.0707x over previous
#include <cuda_runtime.h>
#include <math_constants.h>
#include <cstdint>

#define BB 32
#define SS 480
#define DD 512
#define HH 8
#define DK 64
#define ML 500
#define QT 32
#define JT 128
#define QB 64       // scores row band
#define QBP 68      // qsT row stride
#define JTP 132
#define PVQ 128

__device__ float g_q[BB*HH*SS*DK];
__device__ float g_k[BB*HH*SS*DK];
__device__ float g_v[BB*HH*SS*DK];
__device__ float g_ctx[(size_t)BB*SS*DD];
__device__ float g_p[(size_t)BB*HH*SS*SS];   // raw scores, then probs in-place

// ---------------------------------------------------------------------------
// Kernel 1: fused QKV projection (R14 version — known good).
// ---------------------------------------------------------------------------
__global__ __launch_bounds__(128) void proj_qkv(
    const float* __restrict__ x,
    const float* __restrict__ wq, const float* __restrict__ bq,
    const float* __restrict__ wk, const float* __restrict__ bk,
    const float* __restrict__ wv, const float* __restrict__ bv)
{
    const int z = blockIdx.z;
    const float* W    = (z == 0) ? wq : (z == 1) ? wk : wv;
    const float* bias = (z == 0) ? bq : (z == 1) ? bk : bv;
    float* Out        = (z == 0) ? g_q : (z == 1) ? g_k : g_v;

    __shared__ float Xs[32][132];
    __shared__ float Ws[32][68];

    const int m0 = blockIdx.x * 64;
    const int n0 = blockIdx.y * 128;
    const int tid = threadIdx.x;

    const int c8 = tid & 7,  xrow = tid >> 3;
    const int wc4 = tid & 15, wk_ = tid >> 4;
    const int ri = tid >> 3, ci = tid & 7;

    float acc[8][8] = {};
    float4 xr[8], wr[4];

#pragma unroll
    for (int rr = 0; rr < 8; rr++)
        xr[rr] = *(const float4*)&x[(size_t)(n0 + xrow + rr*16)*DD + c8*4];
#pragma unroll
    for (int tt = 0; tt < 4; tt++)
        wr[tt] = *(const float4*)&W[(size_t)(wk_ + tt*8)*DD + m0 + wc4*4];

    for (int k0 = 0; k0 < DD; k0 += 32) {
#pragma unroll
        for (int rr = 0; rr < 8; rr++) {
            int r = xrow + rr*16;
            Xs[c8*4+0][r] = xr[rr].x; Xs[c8*4+1][r] = xr[rr].y;
            Xs[c8*4+2][r] = xr[rr].z; Xs[c8*4+3][r] = xr[rr].w;
        }
#pragma unroll
        for (int tt = 0; tt < 4; tt++)
            *(float4*)&Ws[wk_ + tt*8][wc4*4] = wr[tt];
        __syncthreads();

        if (k0 + 32 < DD) {
#pragma unroll
            for (int rr = 0; rr < 8; rr++)
                xr[rr] = *(const float4*)&x[(size_t)(n0 + xrow + rr*16)*DD + k0 + 32 + c8*4];
#pragma unroll
            for (int tt = 0; tt < 4; tt++)
                wr[tt] = *(const float4*)&W[(size_t)(k0 + 32 + wk_ + tt*8)*DD + m0 + wc4*4];
        }

#pragma unroll
        for (int t = 0; t < 32; t++) {
            float4 a0 = *(const float4*)&Xs[t][ri*8];
            float4 a1 = *(const float4*)&Xs[t][ri*8+4];
            float4 b0 = *(const float4*)&Ws[t][ci*8];
            float4 b1 = *(const float4*)&Ws[t][ci*8+4];
            float av[8] = {a0.x,a0.y,a0.z,a0.w,a1.x,a1.y,a1.z,a1.w};
            float bw[8] = {b0.x,b0.y,b0.z,b0.w,b1.x,b1.y,b1.z,b1.w};
#pragma unroll
            for (int i = 0; i < 8; i++)
#pragma unroll
                for (int j = 0; j < 8; j++)
                    acc[i][j] += av[i] * bw[j];
        }
        __syncthreads();
    }

    const int h = m0 >> 6;
    const int d = ci*8;
    float4 bb0 = *(const float4*)&bias[m0 + d];
    float4 bb1 = *(const float4*)&bias[m0 + d + 4];
#pragma unroll
    for (int u = 0; u < 8; u++) {
        int n = n0 + ri*8 + u;
        int b = n / SS, s = n % SS;
        float* dst = &Out[(((size_t)b*HH + h)*SS + s)*DK + d];
        *(float4*)&dst[0] = make_float4(acc[u][0]+bb0.x, acc[u][1]+bb0.y,
                                        acc[u][2]+bb0.z, acc[u][3]+bb0.w);
        *(float4*)&dst[4] = make_float4(acc[u][4]+bb1.x, acc[u][5]+bb1.y,
                                        acc[u][6]+bb1.z, acc[u][7]+bb1.w);
    }
}

// ---------------------------------------------------------------------------
// Kernel 2a: scores GEMM (R14 version — known good).
// ---------------------------------------------------------------------------
__global__ __launch_bounds__(256) void scores_gemm(
    const float* __restrict__ rel_bias)
{
    __shared__ float qsT[64*QBP];
    __shared__ float kvb[64*JTP];

    const int i0 = blockIdx.x * QB;
    const int h  = blockIdx.y;
    const int b  = blockIdx.z;
    const int tid = threadIdx.x;

    const int rows   = min(QB, SS - i0);
    const int jcount = min(i0 + QB, SS);
    const int ntile  = (jcount + JT - 1) / JT;

    const float* qg = g_q + (((size_t)b*HH + h)*SS + i0)*DK;
    const float* kg = g_k + (((size_t)b*HH + h)*SS)*DK;
    float* sg = g_p + (((size_t)b*HH + h)*SS + i0)*SS;

#pragma unroll
    for (int it = 0; it < 16; it++) {
        int idx = tid + it*256;
        int i = idx >> 6, t = idx & 63;
        qsT[t*QBP + i] = (i < rows) ? qg[(size_t)i*DK + t] : 0.f;
    }

    const int ig = tid >> 4;
    const int jg = tid & 15;

    for (int jt = 0; jt < ntile; jt++) {
        const int j0 = jt * JT;
        __syncthreads();
#pragma unroll
        for (int it = 0; it < 32; it++) {
            int idx = tid + it*256;
            int jl = idx >> 6, t = idx & 63;
            int j = j0 + jl;
            kvb[t*JTP + jl] = (j < SS) ? kg[(size_t)j*DK + t] : 0.f;
        }
        __syncthreads();

        float acc[4][8] = {};
#pragma unroll
        for (int t = 0; t < 64; t++) {
            float4 a4 = *(const float4*)&qsT[t*QBP + ig*4];
            float4 b0 = *(const float4*)&kvb[t*JTP + jg*4];
            float4 b1 = *(const float4*)&kvb[t*JTP + 64 + jg*4];
            float av[4] = {a4.x, a4.y, a4.z, a4.w};
            float bw[8] = {b0.x,b0.y,b0.z,b0.w,b1.x,b1.y,b1.z,b1.w};
#pragma unroll
            for (int i = 0; i < 4; i++)
#pragma unroll
                for (int c = 0; c < 8; c++)
                    acc[i][c] += av[i] * bw[c];
        }

#pragma unroll
        for (int ii = 0; ii < 4; ii++) {
            const int il = ig*4 + ii;
            if (il >= rows) break;
            const int i = i0 + il;
            const float* brow = rel_bias + ((size_t)h*ML + i)*ML;
            float* srow = sg + (size_t)il*SS;
#pragma unroll
            for (int half = 0; half < 2; half++) {
                const int jb = j0 + half*64 + jg*4;
                float vals[4];
#pragma unroll
                for (int jj = 0; jj < 4; jj++) {
                    int j = jb + jj;
                    vals[jj] = (j <= i && j < SS) ? acc[ii][half*4+jj]*0.125f + brow[j]
                                                  : -CUDART_INF_F;
                }
                if (jb + 3 < SS)
                    *(float4*)&srow[jb] = make_float4(vals[0], vals[1], vals[2], vals[3]);
                else {
#pragma unroll
                    for (int jj = 0; jj < 4; jj++)
                        if (jb + jj < SS) srow[jb + jj] = vals[jj];
                }
            }
        }
    }
}

// ---------------------------------------------------------------------------
// Kernel 2b: row softmax, in place (R14 version).  Writes zeros above diag.
// ---------------------------------------------------------------------------
__global__ __launch_bounds__(256) void softmax_row()
{
    const int gid  = blockIdx.x * 8 + (threadIdx.x >> 5);
    const int lane = threadIdx.x & 31;
    const int i = gid % SS;
    const int n = i + 1;

    float* row = g_p + (size_t)gid * SS;

    float v[15];
    float m = -CUDART_INF_F;
#pragma unroll
    for (int k = 0; k < 15; k++) {
        int j = lane + k*32;
        v[k] = (j < n) ? row[j] : -CUDART_INF_F;
        m = fmaxf(m, v[k]);
    }
#pragma unroll
    for (int o = 16; o; o >>= 1) m = fmaxf(m, __shfl_xor_sync(0xffffffffu, m, o));

    float s = 0.f;
#pragma unroll
    for (int k = 0; k < 15; k++) {
        int j = lane + k*32;
        v[k] = (j < n) ? __expf(v[k] - m) : 0.f;
        s += v[k];
    }
#pragma unroll
    for (int o = 16; o; o >>= 1) s += __shfl_xor_sync(0xffffffffu, s, o);
    float inv = 1.f / s;

#pragma unroll
    for (int k = 0; k < 15; k++) {
        int j = lane + k*32;
        row[j] = v[k] * inv;
    }
}

// ---------------------------------------------------------------------------
// Kernel 3: attn mean over heads (unchanged — 75% DRAM).
// ---------------------------------------------------------------------------
__global__ __launch_bounds__(256) void mean_kernel(float* __restrict__ out_attn)
{
    const int gid = blockIdx.x * 256 + threadIdx.x;
    const int j4  = gid % (SS/4);
    int rest = gid / (SS/4);
    const int i = rest % SS;
    const int b = rest / SS;

    const int i0 = (i >> 5) << 5;
    const int jcap = min(SS, (((i0 + QT) + JT - 1) / JT) * JT);

    float4 s = make_float4(0.f, 0.f, 0.f, 0.f);
    if (j4*4 < jcap) {
        const float* base = g_p + (((size_t)b*HH)*SS + i)*SS + j4*4;
#pragma unroll
        for (int h = 0; h < HH; h++) {
            float4 v = *(const float4*)(base + (size_t)h*SS*SS);
            s.x += v.x; s.y += v.y; s.z += v.z; s.w += v.w;
        }
        s.x *= 0.125f; s.y *= 0.125f; s.z *= 0.125f; s.w *= 0.125f;
    }
    *(float4*)&out_attn[((size_t)b*SS + i)*SS + j4*4] = s;
}

// ---------------------------------------------------------------------------
// Kernel 4: ctx = P @ V.  NEW: P stored row-major (no transpose).
// Stores: float4 coalesced, conflict-free.  Compute reads P via warp
// broadcast (2 distinct addresses per warp), V as before.
// 256 thr, C tile 128x64, thread tile 8r x 4d, j in float4 steps.
// ---------------------------------------------------------------------------
__global__ __launch_bounds__(256, 2) void pv_kernel()
{
    extern __shared__ float pvsm[];
    float* ps = pvsm;            // PVQ x JT  (64 KB)
    float* vs = ps + PVQ*JT;     // JT x 64   (32 KB)

    const int i0 = blockIdx.x * PVQ;
    const int h  = blockIdx.y;
    const int b  = blockIdx.z;
    const int tid = threadIdx.x;

    const int jcount = min(i0 + PVQ, SS);
    const int ntile  = (jcount + JT - 1) / JT;

    const float* vg = g_v + (((size_t)b*HH + h)*SS)*DK;
    const float* pg = g_p + (((size_t)b*HH + h)*SS + i0)*SS;

    const int rg = tid >> 4;      // 16 rowgroups of 8  (128 rows)
    const int cg = tid & 15;      // 16 colgroups of 4  (64 cols)

    float acc[8][4] = {};

    for (int jt = 0; jt < ntile; jt++) {
        const int j0 = jt * JT;
        __syncthreads();
        // V tile [j][d]: 2048 float4 / 256 thr = 8 iters
#pragma unroll
        for (int it = 0; it < 8; it++) {
            int idx = tid + it*256;
            int j = idx >> 4, d4 = idx & 15;
            float4 v = (j0 + j < SS)
                ? *(const float4*)&vg[(size_t)(j0 + j)*DK + d4*4]
                : make_float4(0.f,0.f,0.f,0.f);
            *(float4*)&vs[j*64 + d4*4] = v;
        }
        // P tile [r][j] row-major: 128x32 float4 = 4096 float4 / 256 = 16 iters.
        // SS is a multiple of 4, so float4 bounds are exact.
#pragma unroll
        for (int it = 0; it < 16; it++) {
            int idx = tid + it*256;
            int r = idx >> 5, j4 = idx & 31;
            float4 p = (i0 + r < SS && j0 + j4*4 < SS)
                ? *(const float4*)&pg[(size_t)r*SS + j0 + j4*4]
                : make_float4(0.f,0.f,0.f,0.f);
            *(float4*)&ps[r*JT + j4*4] = p;
        }
        __syncthreads();

#pragma unroll 2
        for (int j4 = 0; j4 < 32; j4++) {
            const int jj = j4*4;
            float4 p[8];
#pragma unroll
            for (int i = 0; i < 8; i++)
                p[i] = *(const float4*)&ps[(rg*8 + i)*JT + jj];
            float4 v0 = *(const float4*)&vs[(jj+0)*64 + cg*4];
            float4 v1 = *(const float4*)&vs[(jj+1)*64 + cg*4];
            float4 v2 = *(const float4*)&vs[(jj+2)*64 + cg*4];
            float4 v3 = *(const float4*)&vs[(jj+3)*64 + cg*4];
#pragma unroll
            for (int i = 0; i < 8; i++) {
                acc[i][0] += p[i].x*v0.x + p[i].y*v1.x + p[i].z*v2.x + p[i].w*v3.x;
                acc[i][1] += p[i].x*v0.y + p[i].y*v1.y + p[i].z*v2.y + p[i].w*v3.y;
                acc[i][2] += p[i].x*v0.z + p[i].y*v1.z + p[i].z*v2.z + p[i].w*v3.z;
                acc[i][3] += p[i].x*v0.w + p[i].y*v1.w + p[i].z*v2.w + p[i].w*v3.w;
            }
        }
    }

#pragma unroll
    for (int i = 0; i < 8; i++) {
        int row = i0 + rg*8 + i;
        if (row < SS) {
            float* dst = g_ctx + ((size_t)b*SS + row)*DD + h*DK + cg*4;
            *(float4*)dst = make_float4(acc[i][0], acc[i][1], acc[i][2], acc[i][3]);
        }
    }
}

// ---------------------------------------------------------------------------
// Kernel 5: output projection (R14 version).
// ---------------------------------------------------------------------------
__global__ __launch_bounds__(128) void out_proj(
    const float* __restrict__ wo, const float* __restrict__ bo,
    float* __restrict__ out)
{
    __shared__ float Xs[32][132];
    __shared__ float Ws[32][68];

    const int m0 = blockIdx.x * 64;
    const int n0 = blockIdx.y * 128;
    const int tid = threadIdx.x;

    const int c8 = tid & 7,  xrow = tid >> 3;
    const int wc4 = tid & 15, wk_ = tid >> 4;
    const int ri = tid >> 3, ci = tid & 7;

    float acc[8][8] = {};
    float4 xr[8], wr[4];

#pragma unroll
    for (int rr = 0; rr < 8; rr++)
        xr[rr] = *(const float4*)&g_ctx[(size_t)(n0 + xrow + rr*16)*DD + c8*4];
#pragma unroll
    for (int tt = 0; tt < 4; tt++)
        wr[tt] = *(const float4*)&wo[(size_t)(wk_ + tt*8)*DD + m0 + wc4*4];

    for (int k0 = 0; k0 < DD; k0 += 32) {
#pragma unroll
        for (int rr = 0; rr < 8; rr++) {
            int r = xrow + rr*16;
            Xs[c8*4+0][r] = xr[rr].x; Xs[c8*4+1][r] = xr[rr].y;
            Xs[c8*4+2][r] = xr[rr].z; Xs[c8*4+3][r] = xr[rr].w;
        }
#pragma unroll
        for (int tt = 0; tt < 4; tt++)
            *(float4*)&Ws[wk_ + tt*8][wc4*4] = wr[tt];
        __syncthreads();

        if (k0 + 32 < DD) {
#pragma unroll
            for (int rr = 0; rr < 8; rr++)
                xr[rr] = *(const float4*)&g_ctx[(size_t)(n0 + xrow + rr*16)*DD + k0 + 32 + c8*4];
#pragma unroll
            for (int tt = 0; tt < 4; tt++)
                wr[tt] = *(const float4*)&wo[(size_t)(k0 + 32 + wk_ + tt*8)*DD + m0 + wc4*4];
        }

#pragma unroll
        for (int t = 0; t < 32; t++) {
            float4 a0 = *(const float4*)&Xs[t][ri*8];
            float4 a1 = *(const float4*)&Xs[t][ri*8+4];
            float4 b0 = *(const float4*)&Ws[t][ci*8];
            float4 b1 = *(const float4*)&Ws[t][ci*8+4];
            float av[8] = {a0.x,a0.y,a0.z,a0.w,a1.x,a1.y,a1.z,a1.w};
            float bw[8] = {b0.x,b0.y,b0.z,b0.w,b1.x,b1.y,b1.z,b1.w};
#pragma unroll
            for (int i = 0; i < 8; i++)
#pragma unroll
                for (int j = 0; j < 8; j++)
                    acc[i][j] += av[i] * bw[j];
        }
        __syncthreads();
    }

    const int d = ci*8;
    float4 bb0 = *(const float4*)&bo[m0 + d];
    float4 bb1 = *(const float4*)&bo[m0 + d + 4];
#pragma unroll
    for (int u = 0; u < 8; u++) {
        int n = n0 + ri*8 + u;
        float* dst = &out[(size_t)n*DD + m0 + d];
        *(float4*)&dst[0] = make_float4(acc[u][0]+bb0.x, acc[u][1]+bb0.y,
                                        acc[u][2]+bb0.z, acc[u][3]+bb0.w);
        *(float4*)&dst[4] = make_float4(acc[u][4]+bb1.x, acc[u][5]+bb1.y,
                                        acc[u][6]+bb1.z, acc[u][7]+bb1.w);
    }
}

// ---------------------------------------------------------------------------

static const int PV_SMEM = (PVQ*JT + JT*64) * (int)sizeof(float);   // 98304

extern "C" void kernel_launch(void* const* d_in, const int* in_sizes, int n_in,
                              void* d_out, int out_size) {
    const float* x  = (const float*)d_in[0];
    const float* wq = (const float*)d_in[1];
    const float* bq = (const float*)d_in[2];
    const float* wk = (const float*)d_in[3];
    const float* bk = (const float*)d_in[4];
    const float* wv = (const float*)d_in[5];
    const float* bv = (const float*)d_in[6];
    const float* wo = (const float*)d_in[7];
    const float* bo = (const float*)d_in[8];
    const float* rb = (const float*)d_in[9];

    float* out      = (float*)d_out;
    float* out_attn = out + (size_t)BB*SS*DD;

    cudaFuncSetAttribute(pv_kernel, cudaFuncAttributeMaxDynamicSharedMemorySize, PV_SMEM);

    proj_qkv<<<dim3(DD/64, (BB*SS)/128, 3), 128>>>(x, wq, bq, wk, bk, wv, bv);

    scores_gemm<<<dim3((SS + QB - 1)/QB, HH, BB), 256>>>(rb);
    softmax_row<<<(BB*HH*SS)/8, 256>>>();

    mean_kernel<<<(BB*SS*(SS/4))/256, 256>>>(out_attn);

    pv_kernel<<<dim3((SS + PVQ - 1)/PVQ, HH, BB), 256, PV_SMEM>>>();

    out_proj<<<dim3(DD/64, (BB*SS)/128), 128>>>(wo, bo, out);
}